// round 1
// baseline (speedup 1.0000x reference)
#include <cuda_runtime.h>
#include <cuda_bf16.h>
#include <cstdint>

#define NTOK 16384
#define HD   2048
#define NE   8
#define BD   128
#define EPSF 1e-6f

// ---------------- static device scratch (no allocations allowed) ----------------
__device__ __nv_bfloat16 g_xb [NTOK * HD];          // 64 MB  x in bf16
__device__ __nv_bfloat16 g_w1b[NE * BD * HD];       // 4 MB
__device__ __nv_bfloat16 g_w2b[NE * HD * BD];       // 4 MB
__device__ __nv_bfloat16 g_h  [NE * NTOK * BD];     // 33.5 MB  relu(x W1^T + b1), per (expert, list pos)
__device__ __nv_bfloat16 g_scr[2 * NTOK * HD];      // 128 MB  per (token,k) expert output (weighted)
__device__ float g_w   [NTOK * NE];                 // combine weights (0 if not selected)
__device__ float g_prob[NTOK * NE];                 // softmax probs (for aux loss)
__device__ int   g_tok [NE * NTOK];                 // expert -> list of (token*2+k)
__device__ int   g_cnt [NE];

// ---------------- helpers ----------------
static __device__ __forceinline__ uint32_t smem_u32(const void* p) {
    return (uint32_t)__cvta_generic_to_shared(p);
}
#define CP16(dst_u32, src_ptr) \
    asm volatile("cp.async.cg.shared.global [%0], [%1], 16;\n" :: "r"(dst_u32), "l"(src_ptr))
#define CP_COMMIT() asm volatile("cp.async.commit_group;\n" ::)
#define CP_WAIT(n)  asm volatile("cp.async.wait_group %0;\n" :: "n"(n))

static __device__ __forceinline__ void ldm4(uint32_t& r0, uint32_t& r1, uint32_t& r2, uint32_t& r3,
                                            uint32_t addr) {
    asm volatile("ldmatrix.sync.aligned.m8n8.x4.shared.b16 {%0,%1,%2,%3}, [%4];"
                 : "=r"(r0), "=r"(r1), "=r"(r2), "=r"(r3) : "r"(addr));
}
static __device__ __forceinline__ void mma16816(float* c, const uint32_t* a, const uint32_t* b) {
    asm volatile(
        "mma.sync.aligned.m16n8k16.row.col.f32.bf16.bf16.f32 "
        "{%0,%1,%2,%3}, {%4,%5,%6,%7}, {%8,%9}, {%0,%1,%2,%3};"
        : "+f"(c[0]), "+f"(c[1]), "+f"(c[2]), "+f"(c[3])
        : "r"(a[0]), "r"(a[1]), "r"(a[2]), "r"(a[3]), "r"(b[0]), "r"(b[1]));
}

// ---------------- kernel 0: zero counters ----------------
__global__ void k_init() {
    if (threadIdx.x < NE) g_cnt[threadIdx.x] = 0;
}

// ---------------- kernel 1: weights -> bf16 ----------------
__global__ void k_convert(const float* __restrict__ W1, const float* __restrict__ W2) {
    int total = NE * BD * HD;  // == NE*HD*BD
    for (int i = blockIdx.x * blockDim.x + threadIdx.x; i < total; i += gridDim.x * blockDim.x) {
        g_w1b[i] = __float2bfloat16(W1[i]);
        g_w2b[i] = __float2bfloat16(W2[i]);
    }
}

// ---------------- kernel 2: router (1 token per block, 8 warps = 8 experts) ----------------
__global__ __launch_bounds__(256) void k_router(const float* __restrict__ x,
                                                const float* __restrict__ skin,
                                                const float* __restrict__ Wimg,
                                                const float* __restrict__ Wskin) {
    int n = blockIdx.x;
    int tid = threadIdx.x, lane = tid & 31, wid = tid >> 5;

    const float4* xr = (const float4*)(x + (size_t)n * HD);
    const float4* wr = (const float4*)(Wimg + (size_t)wid * HD);
    float acc = 0.f;
#pragma unroll 4
    for (int j = lane; j < HD / 4; j += 32) {
        float4 a = xr[j];
        float4 b = wr[j];
        acc += a.x * b.x + a.y * b.y + a.z * b.z + a.w * b.w;
    }
#pragma unroll
    for (int o = 16; o; o >>= 1) acc += __shfl_xor_sync(0xffffffffu, acc, o);

    __shared__ float lg[NE];
    if (lane == 0) {
        float s = skin[n * 3 + 0] * Wskin[wid * 3 + 0] +
                  skin[n * 3 + 1] * Wskin[wid * 3 + 1] +
                  skin[n * 3 + 2] * Wskin[wid * 3 + 2];
        lg[wid] = acc + s;
    }
    // bf16 copy of x row (cache-hot)
    for (int j = tid; j < HD; j += 256) g_xb[(size_t)n * HD + j] = __float2bfloat16(x[(size_t)n * HD + j]);
    __syncthreads();

    if (tid == 0) {
        float p[NE];
        float mx = lg[0];
#pragma unroll
        for (int e = 1; e < NE; e++) mx = fmaxf(mx, lg[e]);
        float ssum = 0.f;
#pragma unroll
        for (int e = 0; e < NE; e++) { p[e] = expf(lg[e] - mx); ssum += p[e]; }
        float inv = 1.f / ssum;
#pragma unroll
        for (int e = 0; e < NE; e++) p[e] *= inv;

        // top-2 (ties -> lower index, matching lax.top_k)
        int i1 = 0;
#pragma unroll
        for (int e = 1; e < NE; e++) if (p[e] > p[i1]) i1 = e;
        int i2 = (i1 == 0) ? 1 : 0;
#pragma unroll
        for (int e = 0; e < NE; e++) { if (e != i1 && p[e] > p[i2]) i2 = e; }

        float v1 = p[i1], v2 = p[i2];
        float wn = 1.f / (v1 + v2 + EPSF);
        float wv[NE];
#pragma unroll
        for (int e = 0; e < NE; e++) wv[e] = 0.f;
        wv[i1] = v1 * wn;
        wv[i2] = v2 * wn;
#pragma unroll
        for (int e = 0; e < NE; e++) { g_w[n * NE + e] = wv[e]; g_prob[n * NE + e] = p[e]; }

        int p1 = atomicAdd(&g_cnt[i1], 1); g_tok[i1 * NTOK + p1] = n * 2 + 0;
        int p2 = atomicAdd(&g_cnt[i2], 1); g_tok[i2 * NTOK + p2] = n * 2 + 1;
    }
}

// ---------------- kernel 3: GEMM1  h = relu(Xg @ W1^T + b1)  [Me x 2048] x [128 x 2048] ----------------
__global__ __launch_bounds__(256) void k_gemm1(const float* __restrict__ b1) {
    int e = blockIdx.z;
    int cnt = g_cnt[e];
    int m0 = blockIdx.y * 128;
    if (m0 >= cnt) return;

    __shared__ __nv_bfloat16 As[2][128][40];
    __shared__ __nv_bfloat16 Bs[2][128][40];

    int tid = threadIdx.x, lane = tid & 31, wid = tid >> 5;
    int wm = wid >> 1, wn = wid & 1;  // 4 x 2 warp grid; warp tile 32(M) x 64(N)

    int rA0 = tid >> 2, rA1 = 64 + (tid >> 2), ch = tid & 3;
    int tok0 = (m0 + rA0 < cnt) ? (g_tok[e * NTOK + m0 + rA0] >> 1) : 0;
    int tok1 = (m0 + rA1 < cnt) ? (g_tok[e * NTOK + m0 + rA1] >> 1) : 0;

    float c[2][8][4];
#pragma unroll
    for (int mi = 0; mi < 2; mi++)
#pragma unroll
        for (int ni = 0; ni < 8; ni++)
#pragma unroll
            for (int q = 0; q < 4; q++) c[mi][ni][q] = 0.f;

    const int NK = HD / 32;  // 64

    // prologue
    {
        int k0 = 0;
        CP16(smem_u32(&As[0][rA0][ch * 8]), g_xb + (size_t)tok0 * HD + k0 + ch * 8);
        CP16(smem_u32(&As[0][rA1][ch * 8]), g_xb + (size_t)tok1 * HD + k0 + ch * 8);
        CP16(smem_u32(&Bs[0][rA0][ch * 8]), g_w1b + ((size_t)e * BD + rA0) * HD + k0 + ch * 8);
        CP16(smem_u32(&Bs[0][rA1][ch * 8]), g_w1b + ((size_t)e * BD + rA1) * HD + k0 + ch * 8);
        CP_COMMIT();
    }

    for (int it = 0; it < NK; it++) {
        if (it + 1 < NK) {
            int s = (it + 1) & 1, k0 = (it + 1) * 32;
            CP16(smem_u32(&As[s][rA0][ch * 8]), g_xb + (size_t)tok0 * HD + k0 + ch * 8);
            CP16(smem_u32(&As[s][rA1][ch * 8]), g_xb + (size_t)tok1 * HD + k0 + ch * 8);
            CP16(smem_u32(&Bs[s][rA0][ch * 8]), g_w1b + ((size_t)e * BD + rA0) * HD + k0 + ch * 8);
            CP16(smem_u32(&Bs[s][rA1][ch * 8]), g_w1b + ((size_t)e * BD + rA1) * HD + k0 + ch * 8);
            CP_COMMIT();
            CP_WAIT(1);
        } else {
            CP_WAIT(0);
        }
        __syncthreads();

        int s = it & 1;
#pragma unroll
        for (int kk = 0; kk < 2; kk++) {
            uint32_t a[2][4];
#pragma unroll
            for (int mi = 0; mi < 2; mi++) {
                uint32_t ad = smem_u32(&As[s][wm * 32 + mi * 16 + (lane & 15)][kk * 16 + ((lane >> 4) << 3)]);
                ldm4(a[mi][0], a[mi][1], a[mi][2], a[mi][3], ad);
            }
            uint32_t b[8][2];
#pragma unroll
            for (int nj = 0; nj < 4; nj++) {
                uint32_t ad = smem_u32(&Bs[s][wn * 64 + nj * 16 + (lane & 7) + ((lane >> 4) << 3)]
                                          [kk * 16 + (((lane >> 3) & 1) << 3)]);
                uint32_t r0, r1, r2, r3;
                ldm4(r0, r1, r2, r3, ad);
                b[2 * nj][0] = r0; b[2 * nj][1] = r1;
                b[2 * nj + 1][0] = r2; b[2 * nj + 1][1] = r3;
            }
#pragma unroll
            for (int mi = 0; mi < 2; mi++)
#pragma unroll
                for (int ni = 0; ni < 8; ni++) mma16816(c[mi][ni], a[mi], b[ni]);
        }
        __syncthreads();
    }

    // epilogue: relu(+b1) -> bf16 h rows
    const float* b1e = b1 + e * BD;
#pragma unroll
    for (int mi = 0; mi < 2; mi++) {
#pragma unroll
        for (int rr = 0; rr < 2; rr++) {
            int gr = m0 + wm * 32 + mi * 16 + (lane >> 2) + rr * 8;
            if (gr < cnt) {
                __nv_bfloat16* hp = g_h + ((size_t)e * NTOK + gr) * BD;
#pragma unroll
                for (int ni = 0; ni < 8; ni++) {
                    int col = wn * 64 + ni * 8 + (lane & 3) * 2;
                    float v0 = fmaxf(c[mi][ni][rr * 2 + 0] + b1e[col], 0.f);
                    float v1 = fmaxf(c[mi][ni][rr * 2 + 1] + b1e[col + 1], 0.f);
                    __nv_bfloat162 pk;
                    pk.x = __float2bfloat16(v0);
                    pk.y = __float2bfloat16(v1);
                    *(__nv_bfloat162*)(hp + col) = pk;
                }
            }
        }
    }
}

// ---------------- kernel 4: GEMM2  scr = w * (H @ W2^T + b2)  [Me x 128] x [2048 x 128] ----------------
__global__ __launch_bounds__(256) void k_gemm2(const float* __restrict__ b2) {
    int e = blockIdx.z;
    int cnt = g_cnt[e];
    int m0 = blockIdx.y * 128;
    if (m0 >= cnt) return;
    int n0 = blockIdx.x * 128;

    __shared__ __nv_bfloat16 As[2][128][40];
    __shared__ __nv_bfloat16 Bs[2][128][40];

    int tid = threadIdx.x, lane = tid & 31, wid = tid >> 5;
    int wm = wid >> 1, wn = wid & 1;

    int rA0 = tid >> 2, rA1 = 64 + (tid >> 2), ch = tid & 3;

    float c[2][8][4];
#pragma unroll
    for (int mi = 0; mi < 2; mi++)
#pragma unroll
        for (int ni = 0; ni < 8; ni++)
#pragma unroll
            for (int q = 0; q < 4; q++) c[mi][ni][q] = 0.f;

    const int NK = BD / 32;  // 4

    {
        int k0 = 0;
        CP16(smem_u32(&As[0][rA0][ch * 8]), g_h + ((size_t)e * NTOK + m0 + rA0) * BD + k0 + ch * 8);
        CP16(smem_u32(&As[0][rA1][ch * 8]), g_h + ((size_t)e * NTOK + m0 + rA1) * BD + k0 + ch * 8);
        CP16(smem_u32(&Bs[0][rA0][ch * 8]), g_w2b + ((size_t)e * HD + n0 + rA0) * BD + k0 + ch * 8);
        CP16(smem_u32(&Bs[0][rA1][ch * 8]), g_w2b + ((size_t)e * HD + n0 + rA1) * BD + k0 + ch * 8);
        CP_COMMIT();
    }

    for (int it = 0; it < NK; it++) {
        if (it + 1 < NK) {
            int s = (it + 1) & 1, k0 = (it + 1) * 32;
            CP16(smem_u32(&As[s][rA0][ch * 8]), g_h + ((size_t)e * NTOK + m0 + rA0) * BD + k0 + ch * 8);
            CP16(smem_u32(&As[s][rA1][ch * 8]), g_h + ((size_t)e * NTOK + m0 + rA1) * BD + k0 + ch * 8);
            CP16(smem_u32(&Bs[s][rA0][ch * 8]), g_w2b + ((size_t)e * HD + n0 + rA0) * BD + k0 + ch * 8);
            CP16(smem_u32(&Bs[s][rA1][ch * 8]), g_w2b + ((size_t)e * HD + n0 + rA1) * BD + k0 + ch * 8);
            CP_COMMIT();
            CP_WAIT(1);
        } else {
            CP_WAIT(0);
        }
        __syncthreads();

        int s = it & 1;
#pragma unroll
        for (int kk = 0; kk < 2; kk++) {
            uint32_t a[2][4];
#pragma unroll
            for (int mi = 0; mi < 2; mi++) {
                uint32_t ad = smem_u32(&As[s][wm * 32 + mi * 16 + (lane & 15)][kk * 16 + ((lane >> 4) << 3)]);
                ldm4(a[mi][0], a[mi][1], a[mi][2], a[mi][3], ad);
            }
            uint32_t b[8][2];
#pragma unroll
            for (int nj = 0; nj < 4; nj++) {
                uint32_t ad = smem_u32(&Bs[s][wn * 64 + nj * 16 + (lane & 7) + ((lane >> 4) << 3)]
                                          [kk * 16 + (((lane >> 3) & 1) << 3)]);
                uint32_t r0, r1, r2, r3;
                ldm4(r0, r1, r2, r3, ad);
                b[2 * nj][0] = r0; b[2 * nj][1] = r1;
                b[2 * nj + 1][0] = r2; b[2 * nj + 1][1] = r3;
            }
#pragma unroll
            for (int mi = 0; mi < 2; mi++)
#pragma unroll
                for (int ni = 0; ni < 8; ni++) mma16816(c[mi][ni], a[mi], b[ni]);
        }
        __syncthreads();
    }

    // epilogue: scr[v] = w * (acc + b2)
    const float* b2e = b2 + (size_t)e * HD;
#pragma unroll
    for (int mi = 0; mi < 2; mi++) {
#pragma unroll
        for (int rr = 0; rr < 2; rr++) {
            int gr = m0 + wm * 32 + mi * 16 + (lane >> 2) + rr * 8;
            if (gr < cnt) {
                int v = g_tok[e * NTOK + gr];
                int n = v >> 1;
                float wv = g_w[n * NE + e];
                __nv_bfloat16* op = g_scr + (size_t)v * HD + n0;
#pragma unroll
                for (int ni = 0; ni < 8; ni++) {
                    int col = wn * 64 + ni * 8 + (lane & 3) * 2;
                    float v0 = wv * (c[mi][ni][rr * 2 + 0] + b2e[n0 + col]);
                    float v1 = wv * (c[mi][ni][rr * 2 + 1] + b2e[n0 + col + 1]);
                    __nv_bfloat162 pk;
                    pk.x = __float2bfloat16(v0);
                    pk.y = __float2bfloat16(v1);
                    *(__nv_bfloat162*)(op + col) = pk;
                }
            }
        }
    }
}

// ---------------- kernel 5: combine  out = x + scr[2n] + scr[2n+1] ----------------
__global__ __launch_bounds__(256) void k_combine(const float* __restrict__ x, float* __restrict__ out) {
    int n = blockIdx.x;
    int tid = threadIdx.x;
    const float4* xr = (const float4*)(x + (size_t)n * HD);
    float4* o = (float4*)(out + (size_t)n * HD);
    const __nv_bfloat162* s0 = (const __nv_bfloat162*)(g_scr + (size_t)(2 * n) * HD);
    const __nv_bfloat162* s1 = (const __nv_bfloat162*)(g_scr + (size_t)(2 * n + 1) * HD);
#pragma unroll
    for (int j = tid; j < HD / 4; j += 256) {
        float4 a = xr[j];
        __nv_bfloat162 p0 = s0[2 * j], p1 = s0[2 * j + 1];
        __nv_bfloat162 q0 = s1[2 * j], q1 = s1[2 * j + 1];
        float4 r;
        r.x = a.x + __bfloat162float(p0.x) + __bfloat162float(q0.x);
        r.y = a.y + __bfloat162float(p0.y) + __bfloat162float(q0.y);
        r.z = a.z + __bfloat162float(p1.x) + __bfloat162float(q1.x);
        r.w = a.w + __bfloat162float(p1.y) + __bfloat162float(q1.y);
        o[j] = r;
    }
}

// ---------------- kernel 6: aux loss ----------------
__global__ void k_aux(float* __restrict__ out, int out_size) {
    if (out_size <= NTOK * HD) return;
    __shared__ float red[256];
    __shared__ float auxs;
    int tid = threadIdx.x;
    if (tid == 0) auxs = 0.f;
    float acc[NE];
#pragma unroll
    for (int e = 0; e < NE; e++) acc[e] = 0.f;
    for (int n = tid; n < NTOK; n += 256) {
#pragma unroll
        for (int e = 0; e < NE; e++) acc[e] += g_prob[n * NE + e];
    }
    __syncthreads();
    for (int e = 0; e < NE; e++) {
        red[tid] = acc[e];
        __syncthreads();
        for (int s = 128; s > 0; s >>= 1) {
            if (tid < s) red[tid] += red[tid + s];
            __syncthreads();
        }
        if (tid == 0) {
            float mp = red[0] / (float)NTOK;
            float mf = (float)g_cnt[e] / (float)NTOK;
            auxs += mp * mf;
        }
        __syncthreads();
    }
    if (tid == 0) out[(size_t)NTOK * HD] = auxs * (float)NE;
}

// ---------------- launch ----------------
extern "C" void kernel_launch(void* const* d_in, const int* in_sizes, int n_in,
                              void* d_out, int out_size) {
    const float* x     = (const float*)d_in[0];
    const float* skin  = (const float*)d_in[1];
    const float* Wimg  = (const float*)d_in[2];
    const float* Wskin = (const float*)d_in[3];
    const float* W1    = (const float*)d_in[4];
    const float* b1    = (const float*)d_in[5];
    const float* W2    = (const float*)d_in[6];
    const float* b2    = (const float*)d_in[7];
    float* out = (float*)d_out;

    k_init<<<1, 256>>>();
    k_convert<<<2048, 256>>>(W1, W2);
    k_router<<<NTOK, 256>>>(x, skin, Wimg, Wskin);
    k_gemm1<<<dim3(1, NTOK / 128, NE), 256>>>(b1);
    k_gemm2<<<dim3(HD / 128, NTOK / 128, NE), 256>>>(b2);
    k_combine<<<NTOK, 256>>>(x, out);
    k_aux<<<1, 256>>>(out, out_size);
}

// round 3
// speedup vs baseline: 1.0228x; 1.0228x over previous
#include <cuda_runtime.h>
#include <cuda_bf16.h>
#include <cstdint>

#define NTOK 16384
#define HD   2048
#define NE   8
#define BD   128
#define EPSF 1e-6f

// ---------------- static device scratch ----------------
__device__ __nv_bfloat16 g_xb [NTOK * HD];
__device__ __nv_bfloat16 g_w1b[NE * BD * HD];
__device__ __nv_bfloat16 g_w2b[NE * HD * BD];
__device__ __nv_bfloat16 g_h  [NE * NTOK * BD];
__device__ __nv_bfloat16 g_scr[2 * NTOK * HD];
__device__ float g_w   [NTOK * NE];
__device__ float g_prob[NTOK * NE];
__device__ int   g_tok [NE * NTOK];
__device__ int   g_cnt [NE];

// ---------------- helpers ----------------
static __device__ __forceinline__ uint32_t smem_u32(const void* p) {
    return (uint32_t)__cvta_generic_to_shared(p);
}
#define CP16(dst_u32, src_ptr) \
    asm volatile("cp.async.cg.shared.global [%0], [%1], 16;\n" :: "r"(dst_u32), "l"(src_ptr))
#define CP_COMMIT() asm volatile("cp.async.commit_group;\n" ::)
#define CP_WAIT(n)  asm volatile("cp.async.wait_group %0;\n" :: "n"(n))

static __device__ __forceinline__ void ldm4(uint32_t& r0, uint32_t& r1, uint32_t& r2, uint32_t& r3,
                                            uint32_t addr) {
    asm volatile("ldmatrix.sync.aligned.m8n8.x4.shared.b16 {%0,%1,%2,%3}, [%4];"
                 : "=r"(r0), "=r"(r1), "=r"(r2), "=r"(r3) : "r"(addr));
}
static __device__ __forceinline__ void mma16816(float* c, const uint32_t* a, const uint32_t* b) {
    asm volatile(
        "mma.sync.aligned.m16n8k16.row.col.f32.bf16.bf16.f32 "
        "{%0,%1,%2,%3}, {%4,%5,%6,%7}, {%8,%9}, {%0,%1,%2,%3};"
        : "+f"(c[0]), "+f"(c[1]), "+f"(c[2]), "+f"(c[3])
        : "r"(a[0]), "r"(a[1]), "r"(a[2]), "r"(a[3]), "r"(b[0]), "r"(b[1]));
}

// ---------------- kernel 0: zero counters ----------------
__global__ void k_init() {
    if (threadIdx.x < NE) g_cnt[threadIdx.x] = 0;
}

// ---------------- kernel 1: weights -> bf16 ----------------
__global__ void k_convert(const float* __restrict__ W1, const float* __restrict__ W2) {
    int total = NE * BD * HD;
    for (int i = blockIdx.x * blockDim.x + threadIdx.x; i < total; i += gridDim.x * blockDim.x) {
        g_w1b[i] = __float2bfloat16(W1[i]);
        g_w2b[i] = __float2bfloat16(W2[i]);
    }
}

// ---------------- kernel 2: router (8 tokens per block, 8 warps = 8 experts) ----------------
#define RT 8
__global__ __launch_bounds__(256) void k_router(const float* __restrict__ x,
                                                const float* __restrict__ skin,
                                                const float* __restrict__ Wimg,
                                                const float* __restrict__ Wskin) {
    int nb = blockIdx.x * RT;
    int tid = threadIdx.x, lane = tid & 31, wid = tid >> 5;

    __shared__ float lg[RT][NE];

    const float4* wr = (const float4*)(Wimg + (size_t)wid * HD);
#pragma unroll
    for (int t = 0; t < RT; t++) {
        int n = nb + t;
        const float4* xr = (const float4*)(x + (size_t)n * HD);
        float acc = 0.f;
#pragma unroll 4
        for (int j = lane; j < HD / 4; j += 32) {
            float4 a = xr[j];
            float4 b = wr[j];
            acc += a.x * b.x + a.y * b.y + a.z * b.z + a.w * b.w;
        }
#pragma unroll
        for (int o = 16; o; o >>= 1) acc += __shfl_xor_sync(0xffffffffu, acc, o);
        if (lane == 0) {
            float s = skin[n * 3 + 0] * Wskin[wid * 3 + 0] +
                      skin[n * 3 + 1] * Wskin[wid * 3 + 1] +
                      skin[n * 3 + 2] * Wskin[wid * 3 + 2];
            lg[t][wid] = acc + s;
        }
    }

    // bf16 copy of the RT x rows (L1-hot)
    {
        const float4* xs = (const float4*)(x + (size_t)nb * HD);
        __nv_bfloat162* xd = (__nv_bfloat162*)(g_xb + (size_t)nb * HD);
        for (int i = tid; i < RT * HD / 4; i += 256) {
            float4 a = xs[i];
            __nv_bfloat162 p0, p1;
            p0.x = __float2bfloat16(a.x); p0.y = __float2bfloat16(a.y);
            p1.x = __float2bfloat16(a.z); p1.y = __float2bfloat16(a.w);
            xd[2 * i] = p0; xd[2 * i + 1] = p1;
        }
    }
    __syncthreads();

    if (tid < RT) {
        int t = tid, n = nb + t;
        float p[NE];
        float mx = lg[t][0];
#pragma unroll
        for (int e = 1; e < NE; e++) mx = fmaxf(mx, lg[t][e]);
        float ssum = 0.f;
#pragma unroll
        for (int e = 0; e < NE; e++) { p[e] = expf(lg[t][e] - mx); ssum += p[e]; }
        float inv = 1.f / ssum;
#pragma unroll
        for (int e = 0; e < NE; e++) p[e] *= inv;

        int i1 = 0;
#pragma unroll
        for (int e = 1; e < NE; e++) if (p[e] > p[i1]) i1 = e;
        int i2 = (i1 == 0) ? 1 : 0;
#pragma unroll
        for (int e = 0; e < NE; e++) { if (e != i1 && p[e] > p[i2]) i2 = e; }

        float v1 = p[i1], v2 = p[i2];
        float wn = 1.f / (v1 + v2 + EPSF);
        float wv[NE];
#pragma unroll
        for (int e = 0; e < NE; e++) wv[e] = 0.f;
        wv[i1] = v1 * wn;
        wv[i2] = v2 * wn;
#pragma unroll
        for (int e = 0; e < NE; e++) { g_w[n * NE + e] = wv[e]; g_prob[n * NE + e] = p[e]; }

        int p1 = atomicAdd(&g_cnt[i1], 1); g_tok[i1 * NTOK + p1] = n * 2 + 0;
        int p2 = atomicAdd(&g_cnt[i2], 1); g_tok[i2 * NTOK + p2] = n * 2 + 1;
    }
}

// ---------------- kernel 3: GEMM1  h = relu(Xg @ W1^T + b1) ; 4-stage pipeline ----------------
#define G1_STAGES 4
#define G1_SMEM (G1_STAGES * 128 * 40 * 2 * 2)  // bytes: A + B, 4 stages
__global__ __launch_bounds__(256) void k_gemm1(const float* __restrict__ b1) {
    extern __shared__ __align__(16) char smraw1[];
    __nv_bfloat16 (*As)[128][40] = (__nv_bfloat16 (*)[128][40])smraw1;
    __nv_bfloat16 (*Bs)[128][40] =
        (__nv_bfloat16 (*)[128][40])(smraw1 + G1_STAGES * 128 * 40 * 2);

    int e = blockIdx.z;
    int cnt = g_cnt[e];
    int m0 = blockIdx.y * 128;
    if (m0 >= cnt) return;

    int tid = threadIdx.x, lane = tid & 31, wid = tid >> 5;
    int wm = wid >> 1, wn = wid & 1;

    int rA0 = tid >> 2, rA1 = 64 + (tid >> 2), ch = tid & 3;
    int tok0 = (m0 + rA0 < cnt) ? (g_tok[e * NTOK + m0 + rA0] >> 1) : 0;
    int tok1 = (m0 + rA1 < cnt) ? (g_tok[e * NTOK + m0 + rA1] >> 1) : 0;

    float c[2][8][4];
#pragma unroll
    for (int mi = 0; mi < 2; mi++)
#pragma unroll
        for (int ni = 0; ni < 8; ni++)
#pragma unroll
            for (int q = 0; q < 4; q++) c[mi][ni][q] = 0.f;

    const int NK = HD / 32;  // 64

#define G1_LOAD(s, k0)                                                                        \
    do {                                                                                      \
        CP16(smem_u32(&As[s][rA0][ch * 8]), g_xb + (size_t)tok0 * HD + (k0) + ch * 8);        \
        CP16(smem_u32(&As[s][rA1][ch * 8]), g_xb + (size_t)tok1 * HD + (k0) + ch * 8);        \
        CP16(smem_u32(&Bs[s][rA0][ch * 8]), g_w1b + ((size_t)e * BD + rA0) * HD + (k0) + ch * 8); \
        CP16(smem_u32(&Bs[s][rA1][ch * 8]), g_w1b + ((size_t)e * BD + rA1) * HD + (k0) + ch * 8); \
    } while (0)

#pragma unroll
    for (int s = 0; s < G1_STAGES - 1; s++) { G1_LOAD(s, s * 32); CP_COMMIT(); }

    for (int it = 0; it < NK; it++) {
        CP_WAIT(G1_STAGES - 2);
        __syncthreads();
        int pf = it + G1_STAGES - 1;
        if (pf < NK) G1_LOAD(pf & (G1_STAGES - 1), pf * 32);
        CP_COMMIT();

        int s = it & (G1_STAGES - 1);
#pragma unroll
        for (int kk = 0; kk < 2; kk++) {
            uint32_t a[2][4];
#pragma unroll
            for (int mi = 0; mi < 2; mi++) {
                uint32_t ad = smem_u32(&As[s][wm * 32 + mi * 16 + (lane & 15)][kk * 16 + ((lane >> 4) << 3)]);
                ldm4(a[mi][0], a[mi][1], a[mi][2], a[mi][3], ad);
            }
            uint32_t b[8][2];
#pragma unroll
            for (int nj = 0; nj < 4; nj++) {
                uint32_t ad = smem_u32(&Bs[s][wn * 64 + nj * 16 + (lane & 7) + ((lane >> 4) << 3)]
                                          [kk * 16 + (((lane >> 3) & 1) << 3)]);
                uint32_t r0, r1, r2, r3;
                ldm4(r0, r1, r2, r3, ad);
                b[2 * nj][0] = r0; b[2 * nj][1] = r1;
                b[2 * nj + 1][0] = r2; b[2 * nj + 1][1] = r3;
            }
#pragma unroll
            for (int mi = 0; mi < 2; mi++)
#pragma unroll
                for (int ni = 0; ni < 8; ni++) mma16816(c[mi][ni], a[mi], b[ni]);
        }
    }

    const float* b1e = b1 + e * BD;
#pragma unroll
    for (int mi = 0; mi < 2; mi++) {
#pragma unroll
        for (int rr = 0; rr < 2; rr++) {
            int gr = m0 + wm * 32 + mi * 16 + (lane >> 2) + rr * 8;
            if (gr < cnt) {
                __nv_bfloat16* hp = g_h + ((size_t)e * NTOK + gr) * BD;
#pragma unroll
                for (int ni = 0; ni < 8; ni++) {
                    int col = wn * 64 + ni * 8 + (lane & 3) * 2;
                    float v0 = fmaxf(c[mi][ni][rr * 2 + 0] + b1e[col], 0.f);
                    float v1 = fmaxf(c[mi][ni][rr * 2 + 1] + b1e[col + 1], 0.f);
                    __nv_bfloat162 pk;
                    pk.x = __float2bfloat16(v0);
                    pk.y = __float2bfloat16(v1);
                    *(__nv_bfloat162*)(hp + col) = pk;
                }
            }
        }
    }
}

// ---------------- kernel 4: GEMM2 persistent over M; B tile resident in smem ----------------
#define NSPLIT 8
#define G2_SMEM ((128 * 136 + 2 * 128 * 136) * 2)  // B + double-buffered A, bytes
__global__ __launch_bounds__(256) void k_gemm2(const float* __restrict__ b2) {
    extern __shared__ __align__(16) char smraw2[];
    __nv_bfloat16 (*Bs)[136] = (__nv_bfloat16 (*)[136])smraw2;
    __nv_bfloat16 (*As)[128][136] = (__nv_bfloat16 (*)[128][136])(smraw2 + 128 * 136 * 2);

    int e = blockIdx.y;
    int n0 = blockIdx.x * 128;
    int cnt = g_cnt[e];
    int nmt = (cnt + 127) >> 7;
    int j0 = blockIdx.z;
    if (j0 >= nmt) return;

    int tid = threadIdx.x, lane = tid & 31, wid = tid >> 5;
    int wm = wid >> 1, wn = wid & 1;

    // B tile load (once): 128 rows x 128 halves -> 16 chunks of 16B per row
    for (int i = tid; i < 2048; i += 256) {
        int r = i >> 4, cc = (i & 15) << 3;
        CP16(smem_u32(&Bs[r][cc]), g_w2b + ((size_t)e * HD + n0 + r) * BD + cc);
    }
    // first A tile
    {
        int m0 = j0 << 7;
        for (int i = tid; i < 2048; i += 256) {
            int r = i >> 4, cc = (i & 15) << 3;
            CP16(smem_u32(&As[0][r][cc]), g_h + ((size_t)e * NTOK + m0 + r) * BD + cc);
        }
    }
    CP_COMMIT();

    const float* b2e = b2 + (size_t)e * HD;
    int s = 0;
    for (int j = j0; j < nmt; j += NSPLIT) {
        int jn = j + NSPLIT;
        CP_WAIT(0);
        __syncthreads();
        if (jn < nmt) {
            int m0n = jn << 7;
            for (int i = tid; i < 2048; i += 256) {
                int r = i >> 4, cc = (i & 15) << 3;
                CP16(smem_u32(&As[s ^ 1][r][cc]), g_h + ((size_t)e * NTOK + m0n + r) * BD + cc);
            }
            CP_COMMIT();
        }

        float c[2][8][4];
#pragma unroll
        for (int mi = 0; mi < 2; mi++)
#pragma unroll
            for (int ni = 0; ni < 8; ni++)
#pragma unroll
                for (int q = 0; q < 4; q++) c[mi][ni][q] = 0.f;

#pragma unroll
        for (int kk = 0; kk < 8; kk++) {
            uint32_t a[2][4];
#pragma unroll
            for (int mi = 0; mi < 2; mi++) {
                uint32_t ad = smem_u32(&As[s][wm * 32 + mi * 16 + (lane & 15)][kk * 16 + ((lane >> 4) << 3)]);
                ldm4(a[mi][0], a[mi][1], a[mi][2], a[mi][3], ad);
            }
            uint32_t b[8][2];
#pragma unroll
            for (int nj = 0; nj < 4; nj++) {
                uint32_t ad = smem_u32(&Bs[wn * 64 + nj * 16 + (lane & 7) + ((lane >> 4) << 3)]
                                          [kk * 16 + (((lane >> 3) & 1) << 3)]);
                uint32_t r0, r1, r2, r3;
                ldm4(r0, r1, r2, r3, ad);
                b[2 * nj][0] = r0; b[2 * nj][1] = r1;
                b[2 * nj + 1][0] = r2; b[2 * nj + 1][1] = r3;
            }
#pragma unroll
            for (int mi = 0; mi < 2; mi++)
#pragma unroll
                for (int ni = 0; ni < 8; ni++) mma16816(c[mi][ni], a[mi], b[ni]);
        }

        // epilogue: scr[v] = w * (acc + b2)
        int m0 = j << 7;
#pragma unroll
        for (int mi = 0; mi < 2; mi++) {
#pragma unroll
            for (int rr = 0; rr < 2; rr++) {
                int gr = m0 + wm * 32 + mi * 16 + (lane >> 2) + rr * 8;
                if (gr < cnt) {
                    int v = g_tok[e * NTOK + gr];
                    int n = v >> 1;
                    float wv = g_w[n * NE + e];
                    __nv_bfloat16* op = g_scr + (size_t)v * HD + n0;
#pragma unroll
                    for (int ni = 0; ni < 8; ni++) {
                        int col = wn * 64 + ni * 8 + (lane & 3) * 2;
                        float v0 = wv * (c[mi][ni][rr * 2 + 0] + b2e[n0 + col]);
                        float v1 = wv * (c[mi][ni][rr * 2 + 1] + b2e[n0 + col + 1]);
                        __nv_bfloat162 pk;
                        pk.x = __float2bfloat16(v0);
                        pk.y = __float2bfloat16(v1);
                        *(__nv_bfloat162*)(op + col) = pk;
                    }
                }
            }
        }
        s ^= 1;
    }
}

// ---------------- kernel 5: combine ----------------
__global__ __launch_bounds__(256) void k_combine(const float* __restrict__ x, float* __restrict__ out) {
    int n = blockIdx.x;
    int tid = threadIdx.x;
    const float4* xr = (const float4*)(x + (size_t)n * HD);
    float4* o = (float4*)(out + (size_t)n * HD);
    const __nv_bfloat162* s0 = (const __nv_bfloat162*)(g_scr + (size_t)(2 * n) * HD);
    const __nv_bfloat162* s1 = (const __nv_bfloat162*)(g_scr + (size_t)(2 * n + 1) * HD);
#pragma unroll
    for (int j = tid; j < HD / 4; j += 256) {
        float4 a = xr[j];
        __nv_bfloat162 p0 = s0[2 * j], p1 = s0[2 * j + 1];
        __nv_bfloat162 q0 = s1[2 * j], q1 = s1[2 * j + 1];
        float4 r;
        r.x = a.x + __bfloat162float(p0.x) + __bfloat162float(q0.x);
        r.y = a.y + __bfloat162float(p0.y) + __bfloat162float(q0.y);
        r.z = a.z + __bfloat162float(p1.x) + __bfloat162float(q1.x);
        r.w = a.w + __bfloat162float(p1.y) + __bfloat162float(q1.y);
        o[j] = r;
    }
}

// ---------------- kernel 6: aux loss ----------------
__global__ void k_aux(float* __restrict__ out, int out_size) {
    if (out_size <= NTOK * HD) return;
    __shared__ float red[256];
    __shared__ float auxs;
    int tid = threadIdx.x;
    if (tid == 0) auxs = 0.f;
    float acc[NE];
#pragma unroll
    for (int e = 0; e < NE; e++) acc[e] = 0.f;
    for (int n = tid; n < NTOK; n += 256) {
#pragma unroll
        for (int e = 0; e < NE; e++) acc[e] += g_prob[n * NE + e];
    }
    __syncthreads();
    for (int e = 0; e < NE; e++) {
        red[tid] = acc[e];
        __syncthreads();
        for (int s = 128; s > 0; s >>= 1) {
            if (tid < s) red[tid] += red[tid + s];
            __syncthreads();
        }
        if (tid == 0) {
            float mp = red[0] / (float)NTOK;
            float mf = (float)g_cnt[e] / (float)NTOK;
            auxs += mp * mf;
        }
        __syncthreads();
    }
    if (tid == 0) out[(size_t)NTOK * HD] = auxs * (float)NE;
}

// ---------------- launch ----------------
extern "C" void kernel_launch(void* const* d_in, const int* in_sizes, int n_in,
                              void* d_out, int out_size) {
    const float* x     = (const float*)d_in[0];
    const float* skin  = (const float*)d_in[1];
    const float* Wimg  = (const float*)d_in[2];
    const float* Wskin = (const float*)d_in[3];
    const float* W1    = (const float*)d_in[4];
    const float* b1    = (const float*)d_in[5];
    const float* W2    = (const float*)d_in[6];
    const float* b2    = (const float*)d_in[7];
    float* out = (float*)d_out;

    cudaFuncSetAttribute(k_gemm1, cudaFuncAttributeMaxDynamicSharedMemorySize, G1_SMEM);
    cudaFuncSetAttribute(k_gemm2, cudaFuncAttributeMaxDynamicSharedMemorySize, G2_SMEM);

    k_init<<<1, 256>>>();
    k_convert<<<2048, 256>>>(W1, W2);
    k_router<<<NTOK / RT, 256>>>(x, skin, Wimg, Wskin);
    k_gemm1<<<dim3(1, NTOK / 128, NE), 256, G1_SMEM>>>(b1);
    k_gemm2<<<dim3(HD / 128, NE, NSPLIT), 256, G2_SMEM>>>(b2);
    k_combine<<<NTOK, 256>>>(x, out);
    k_aux<<<1, 256>>>(out, out_size);
}

// round 4
// speedup vs baseline: 1.0831x; 1.0590x over previous
#include <cuda_runtime.h>
#include <cuda_bf16.h>
#include <cstdint>

#define NTOK 16384
#define HD   2048
#define NE   8
#define BD   128
#define EPSF 1e-6f

// ---------------- static device scratch ----------------
__device__ __nv_bfloat16 g_xb [NTOK * HD];
__device__ __nv_bfloat16 g_w1b[NE * BD * HD];
__device__ __nv_bfloat16 g_w2b[NE * HD * BD];
__device__ __nv_bfloat16 g_h  [NE * NTOK * BD];
__device__ __nv_bfloat16 g_scr[2 * NTOK * HD];
__device__ float g_w   [NTOK * NE];
__device__ float g_prob[NTOK * NE];
__device__ int   g_tok [NE * NTOK];
__device__ int   g_cnt [NE];

// ---------------- helpers ----------------
static __device__ __forceinline__ uint32_t smem_u32(const void* p) {
    return (uint32_t)__cvta_generic_to_shared(p);
}
#define CP16(dst_u32, src_ptr) \
    asm volatile("cp.async.cg.shared.global [%0], [%1], 16;\n" :: "r"(dst_u32), "l"(src_ptr))
#define CP_COMMIT() asm volatile("cp.async.commit_group;\n" ::)
#define CP_WAIT(n)  asm volatile("cp.async.wait_group %0;\n" :: "n"(n))

static __device__ __forceinline__ void ldm4(uint32_t& r0, uint32_t& r1, uint32_t& r2, uint32_t& r3,
                                            uint32_t addr) {
    asm volatile("ldmatrix.sync.aligned.m8n8.x4.shared.b16 {%0,%1,%2,%3}, [%4];"
                 : "=r"(r0), "=r"(r1), "=r"(r2), "=r"(r3) : "r"(addr));
}
static __device__ __forceinline__ void mma16816(float* c, const uint32_t* a, const uint32_t* b) {
    asm volatile(
        "mma.sync.aligned.m16n8k16.row.col.f32.bf16.bf16.f32 "
        "{%0,%1,%2,%3}, {%4,%5,%6,%7}, {%8,%9}, {%0,%1,%2,%3};"
        : "+f"(c[0]), "+f"(c[1]), "+f"(c[2]), "+f"(c[3])
        : "r"(a[0]), "r"(a[1]), "r"(a[2]), "r"(a[3]), "r"(b[0]), "r"(b[1]));
}

// ---------------- kernel 0: zero counters ----------------
__global__ void k_init() {
    if (threadIdx.x < NE) g_cnt[threadIdx.x] = 0;
}

// ---------------- kernel 1: weights -> bf16 ----------------
__global__ void k_convert(const float* __restrict__ W1, const float* __restrict__ W2) {
    int total = NE * BD * HD;
    for (int i = blockIdx.x * blockDim.x + threadIdx.x; i < total; i += gridDim.x * blockDim.x) {
        g_w1b[i] = __float2bfloat16(W1[i]);
        g_w2b[i] = __float2bfloat16(W2[i]);
    }
}

// ---------------- kernel 2: router (8 tokens per block, 8 warps = 8 experts) ----------------
#define RT 8
__global__ __launch_bounds__(256) void k_router(const float* __restrict__ x,
                                                const float* __restrict__ skin,
                                                const float* __restrict__ Wimg,
                                                const float* __restrict__ Wskin) {
    int nb = blockIdx.x * RT;
    int tid = threadIdx.x, lane = tid & 31, wid = tid >> 5;

    __shared__ float lg[RT][NE];

    const float4* wr = (const float4*)(Wimg + (size_t)wid * HD);
#pragma unroll
    for (int t = 0; t < RT; t++) {
        int n = nb + t;
        const float4* xr = (const float4*)(x + (size_t)n * HD);
        float acc = 0.f;
#pragma unroll 4
        for (int j = lane; j < HD / 4; j += 32) {
            float4 a = xr[j];
            float4 b = wr[j];
            acc += a.x * b.x + a.y * b.y + a.z * b.z + a.w * b.w;
        }
#pragma unroll
        for (int o = 16; o; o >>= 1) acc += __shfl_xor_sync(0xffffffffu, acc, o);
        if (lane == 0) {
            float s = skin[n * 3 + 0] * Wskin[wid * 3 + 0] +
                      skin[n * 3 + 1] * Wskin[wid * 3 + 1] +
                      skin[n * 3 + 2] * Wskin[wid * 3 + 2];
            lg[t][wid] = acc + s;
        }
    }

    // bf16 copy of the RT x rows (L1-hot)
    {
        const float4* xs = (const float4*)(x + (size_t)nb * HD);
        __nv_bfloat162* xd = (__nv_bfloat162*)(g_xb + (size_t)nb * HD);
        for (int i = tid; i < RT * HD / 4; i += 256) {
            float4 a = xs[i];
            __nv_bfloat162 p0, p1;
            p0.x = __float2bfloat16(a.x); p0.y = __float2bfloat16(a.y);
            p1.x = __float2bfloat16(a.z); p1.y = __float2bfloat16(a.w);
            xd[2 * i] = p0; xd[2 * i + 1] = p1;
        }
    }
    __syncthreads();

    if (tid < RT) {
        int t = tid, n = nb + t;
        float p[NE];
        float mx = lg[t][0];
#pragma unroll
        for (int e = 1; e < NE; e++) mx = fmaxf(mx, lg[t][e]);
        float ssum = 0.f;
#pragma unroll
        for (int e = 0; e < NE; e++) { p[e] = expf(lg[t][e] - mx); ssum += p[e]; }
        float inv = 1.f / ssum;
#pragma unroll
        for (int e = 0; e < NE; e++) p[e] *= inv;

        int i1 = 0;
#pragma unroll
        for (int e = 1; e < NE; e++) if (p[e] > p[i1]) i1 = e;
        int i2 = (i1 == 0) ? 1 : 0;
#pragma unroll
        for (int e = 0; e < NE; e++) { if (e != i1 && p[e] > p[i2]) i2 = e; }

        float v1 = p[i1], v2 = p[i2];
        float wn = 1.f / (v1 + v2 + EPSF);
        float wv[NE];
#pragma unroll
        for (int e = 0; e < NE; e++) wv[e] = 0.f;
        wv[i1] = v1 * wn;
        wv[i2] = v2 * wn;
#pragma unroll
        for (int e = 0; e < NE; e++) { g_w[n * NE + e] = wv[e]; g_prob[n * NE + e] = p[e]; }

        int p1 = atomicAdd(&g_cnt[i1], 1); g_tok[i1 * NTOK + p1] = n * 2 + 0;
        int p2 = atomicAdd(&g_cnt[i2], 1); g_tok[i2 * NTOK + p2] = n * 2 + 1;
    }
}

// ---------------- kernel 3: GEMM1  h = relu(Xg @ W1^T + b1) ; 4-stage pipeline ----------------
#define G1_STAGES 4
#define G1_SMEM (G1_STAGES * 128 * 40 * 2 * 2)
__global__ __launch_bounds__(256) void k_gemm1(const float* __restrict__ b1) {
    extern __shared__ __align__(16) char smraw1[];
    __nv_bfloat16 (*As)[128][40] = (__nv_bfloat16 (*)[128][40])smraw1;
    __nv_bfloat16 (*Bs)[128][40] =
        (__nv_bfloat16 (*)[128][40])(smraw1 + G1_STAGES * 128 * 40 * 2);

    int e = blockIdx.z;
    int cnt = g_cnt[e];
    int m0 = blockIdx.y * 128;
    if (m0 >= cnt) return;

    int tid = threadIdx.x, lane = tid & 31, wid = tid >> 5;
    int wm = wid >> 1, wn = wid & 1;

    int rA0 = tid >> 2, rA1 = 64 + (tid >> 2), ch = tid & 3;
    int tok0 = (m0 + rA0 < cnt) ? (g_tok[e * NTOK + m0 + rA0] >> 1) : 0;
    int tok1 = (m0 + rA1 < cnt) ? (g_tok[e * NTOK + m0 + rA1] >> 1) : 0;

    float c[2][8][4];
#pragma unroll
    for (int mi = 0; mi < 2; mi++)
#pragma unroll
        for (int ni = 0; ni < 8; ni++)
#pragma unroll
            for (int q = 0; q < 4; q++) c[mi][ni][q] = 0.f;

    const int NK = HD / 32;  // 64

#define G1_LOAD(s, k0)                                                                        \
    do {                                                                                      \
        CP16(smem_u32(&As[s][rA0][ch * 8]), g_xb + (size_t)tok0 * HD + (k0) + ch * 8);        \
        CP16(smem_u32(&As[s][rA1][ch * 8]), g_xb + (size_t)tok1 * HD + (k0) + ch * 8);        \
        CP16(smem_u32(&Bs[s][rA0][ch * 8]), g_w1b + ((size_t)e * BD + rA0) * HD + (k0) + ch * 8); \
        CP16(smem_u32(&Bs[s][rA1][ch * 8]), g_w1b + ((size_t)e * BD + rA1) * HD + (k0) + ch * 8); \
    } while (0)

#pragma unroll
    for (int s = 0; s < G1_STAGES - 1; s++) { G1_LOAD(s, s * 32); CP_COMMIT(); }

    for (int it = 0; it < NK; it++) {
        CP_WAIT(G1_STAGES - 2);
        __syncthreads();
        int pf = it + G1_STAGES - 1;
        if (pf < NK) G1_LOAD(pf & (G1_STAGES - 1), pf * 32);
        CP_COMMIT();

        int s = it & (G1_STAGES - 1);
#pragma unroll
        for (int kk = 0; kk < 2; kk++) {
            uint32_t a[2][4];
#pragma unroll
            for (int mi = 0; mi < 2; mi++) {
                uint32_t ad = smem_u32(&As[s][wm * 32 + mi * 16 + (lane & 15)][kk * 16 + ((lane >> 4) << 3)]);
                ldm4(a[mi][0], a[mi][1], a[mi][2], a[mi][3], ad);
            }
            uint32_t b[8][2];
#pragma unroll
            for (int nj = 0; nj < 4; nj++) {
                uint32_t ad = smem_u32(&Bs[s][wn * 64 + nj * 16 + (lane & 7) + ((lane >> 4) << 3)]
                                          [kk * 16 + (((lane >> 3) & 1) << 3)]);
                uint32_t r0, r1, r2, r3;
                ldm4(r0, r1, r2, r3, ad);
                b[2 * nj][0] = r0; b[2 * nj][1] = r1;
                b[2 * nj + 1][0] = r2; b[2 * nj + 1][1] = r3;
            }
#pragma unroll
            for (int mi = 0; mi < 2; mi++)
#pragma unroll
                for (int ni = 0; ni < 8; ni++) mma16816(c[mi][ni], a[mi], b[ni]);
        }
    }

    const float* b1e = b1 + e * BD;
#pragma unroll
    for (int mi = 0; mi < 2; mi++) {
#pragma unroll
        for (int rr = 0; rr < 2; rr++) {
            int gr = m0 + wm * 32 + mi * 16 + (lane >> 2) + rr * 8;
            if (gr < cnt) {
                __nv_bfloat16* hp = g_h + ((size_t)e * NTOK + gr) * BD;
#pragma unroll
                for (int ni = 0; ni < 8; ni++) {
                    int col = wn * 64 + ni * 8 + (lane & 3) * 2;
                    float v0 = fmaxf(c[mi][ni][rr * 2 + 0] + b1e[col], 0.f);
                    float v1 = fmaxf(c[mi][ni][rr * 2 + 1] + b1e[col + 1], 0.f);
                    __nv_bfloat162 pk;
                    pk.x = __float2bfloat16(v0);
                    pk.y = __float2bfloat16(v1);
                    *(__nv_bfloat162*)(hp + col) = pk;
                }
            }
        }
    }
}

// ---------------- kernel 4: GEMM2 persistent over M; smem-staged coalesced epilogue ----------------
#define NSPLIT 8
#define G2_SMEM ((128 * 136 + 2 * 128 * 136) * 2)  // B + double-buffered A, bytes
__global__ __launch_bounds__(256) void k_gemm2(const float* __restrict__ b2) {
    extern __shared__ __align__(16) char smraw2[];
    __nv_bfloat16 (*Bs)[136] = (__nv_bfloat16 (*)[136])smraw2;
    __nv_bfloat16 (*As)[128][136] = (__nv_bfloat16 (*)[128][136])(smraw2 + 128 * 136 * 2);

    __shared__ int   vrow[128];
    __shared__ float wrow[128];
    __shared__ float b2s[128];

    int e = blockIdx.y;
    int n0 = blockIdx.x * 128;
    int cnt = g_cnt[e];
    int nmt = (cnt + 127) >> 7;
    int j0 = blockIdx.z;
    if (j0 >= nmt) return;

    int tid = threadIdx.x, lane = tid & 31, wid = tid >> 5;
    int wm = wid >> 1, wn = wid & 1;

    // B tile load (once): 128 rows x 128 halves
    for (int i = tid; i < 2048; i += 256) {
        int r = i >> 4, cc = (i & 15) << 3;
        CP16(smem_u32(&Bs[r][cc]), g_w2b + ((size_t)e * HD + n0 + r) * BD + cc);
    }
    // first A tile
    {
        int m0 = j0 << 7;
        for (int i = tid; i < 2048; i += 256) {
            int r = i >> 4, cc = (i & 15) << 3;
            CP16(smem_u32(&As[0][r][cc]), g_h + ((size_t)e * NTOK + m0 + r) * BD + cc);
        }
    }
    CP_COMMIT();
    if (tid < 128) b2s[tid] = b2[(size_t)e * HD + n0 + tid];

    int s = 0;
    for (int j = j0; j < nmt; j += NSPLIT) {
        int m0 = j << 7;
        int jn = j + NSPLIT;
        CP_WAIT(0);
        __syncthreads();
        // per-row token / weight metadata for this tile
        if (tid < 128) {
            int gr = m0 + tid;
            int v = (gr < cnt) ? g_tok[e * NTOK + gr] : 0;
            vrow[tid] = v;
            wrow[tid] = (gr < cnt) ? g_w[(v >> 1) * NE + e] : 0.f;
        }
        if (jn < nmt) {
            int m0n = jn << 7;
            for (int i = tid; i < 2048; i += 256) {
                int r = i >> 4, cc = (i & 15) << 3;
                CP16(smem_u32(&As[s ^ 1][r][cc]), g_h + ((size_t)e * NTOK + m0n + r) * BD + cc);
            }
            CP_COMMIT();
        }

        float c[2][8][4];
#pragma unroll
        for (int mi = 0; mi < 2; mi++)
#pragma unroll
            for (int ni = 0; ni < 8; ni++)
#pragma unroll
                for (int q = 0; q < 4; q++) c[mi][ni][q] = 0.f;

#pragma unroll
        for (int kk = 0; kk < 8; kk++) {
            uint32_t a[2][4];
#pragma unroll
            for (int mi = 0; mi < 2; mi++) {
                uint32_t ad = smem_u32(&As[s][wm * 32 + mi * 16 + (lane & 15)][kk * 16 + ((lane >> 4) << 3)]);
                ldm4(a[mi][0], a[mi][1], a[mi][2], a[mi][3], ad);
            }
            uint32_t b[8][2];
#pragma unroll
            for (int nj = 0; nj < 4; nj++) {
                uint32_t ad = smem_u32(&Bs[wn * 64 + nj * 16 + (lane & 7) + ((lane >> 4) << 3)]
                                          [kk * 16 + (((lane >> 3) & 1) << 3)]);
                uint32_t r0, r1, r2, r3;
                ldm4(r0, r1, r2, r3, ad);
                b[2 * nj][0] = r0; b[2 * nj][1] = r1;
                b[2 * nj + 1][0] = r2; b[2 * nj + 1][1] = r3;
            }
#pragma unroll
            for (int mi = 0; mi < 2; mi++)
#pragma unroll
                for (int ni = 0; ni < 8; ni++) mma16816(c[mi][ni], a[mi], b[ni]);
        }

        // stage C -> As[s] (done reading it), scaled + biased, as bf16
        __syncthreads();
#pragma unroll
        for (int mi = 0; mi < 2; mi++) {
#pragma unroll
            for (int rr = 0; rr < 2; rr++) {
                int lr = wm * 32 + mi * 16 + (lane >> 2) + rr * 8;
                float wv = wrow[lr];
#pragma unroll
                for (int ni = 0; ni < 8; ni++) {
                    int col = wn * 64 + ni * 8 + (lane & 3) * 2;
                    float v0 = wv * (c[mi][ni][rr * 2 + 0] + b2s[col]);
                    float v1 = wv * (c[mi][ni][rr * 2 + 1] + b2s[col + 1]);
                    __nv_bfloat162 pk;
                    pk.x = __float2bfloat16(v0);
                    pk.y = __float2bfloat16(v1);
                    *(__nv_bfloat162*)(&As[s][lr][col]) = pk;
                }
            }
        }
        __syncthreads();

        // coalesced store: 16 lanes cover one 256B row segment
        int lim = cnt - m0;
        for (int i = tid; i < 2048; i += 256) {
            int r = i >> 4, cc = (i & 15) << 3;
            if (r < lim) {
                int v = vrow[r];
                uint4 val = *(const uint4*)(&As[s][r][cc]);
                *(uint4*)(g_scr + (size_t)v * HD + n0 + cc) = val;
            }
        }
        s ^= 1;
    }
}

// ---------------- kernel 5: combine ----------------
__global__ __launch_bounds__(256) void k_combine(const float* __restrict__ x, float* __restrict__ out) {
    int n = blockIdx.x;
    int tid = threadIdx.x;
    const float4* xr = (const float4*)(x + (size_t)n * HD);
    float4* o = (float4*)(out + (size_t)n * HD);
    const __nv_bfloat162* s0 = (const __nv_bfloat162*)(g_scr + (size_t)(2 * n) * HD);
    const __nv_bfloat162* s1 = (const __nv_bfloat162*)(g_scr + (size_t)(2 * n + 1) * HD);
#pragma unroll
    for (int j = tid; j < HD / 4; j += 256) {
        float4 a = xr[j];
        __nv_bfloat162 p0 = s0[2 * j], p1 = s0[2 * j + 1];
        __nv_bfloat162 q0 = s1[2 * j], q1 = s1[2 * j + 1];
        float4 r;
        r.x = a.x + __bfloat162float(p0.x) + __bfloat162float(q0.x);
        r.y = a.y + __bfloat162float(p0.y) + __bfloat162float(q0.y);
        r.z = a.z + __bfloat162float(p1.x) + __bfloat162float(q1.x);
        r.w = a.w + __bfloat162float(p1.y) + __bfloat162float(q1.y);
        o[j] = r;
    }
}

// ---------------- kernel 6: aux loss ----------------
__global__ void k_aux(float* __restrict__ out, int out_size) {
    if (out_size <= NTOK * HD) return;
    __shared__ float red[256];
    __shared__ float auxs;
    int tid = threadIdx.x;
    if (tid == 0) auxs = 0.f;
    float acc[NE];
#pragma unroll
    for (int e = 0; e < NE; e++) acc[e] = 0.f;
    for (int n = tid; n < NTOK; n += 256) {
#pragma unroll
        for (int e = 0; e < NE; e++) acc[e] += g_prob[n * NE + e];
    }
    __syncthreads();
    for (int e = 0; e < NE; e++) {
        red[tid] = acc[e];
        __syncthreads();
        for (int s = 128; s > 0; s >>= 1) {
            if (tid < s) red[tid] += red[tid + s];
            __syncthreads();
        }
        if (tid == 0) {
            float mp = red[0] / (float)NTOK;
            float mf = (float)g_cnt[e] / (float)NTOK;
            auxs += mp * mf;
        }
        __syncthreads();
    }
    if (tid == 0) out[(size_t)NTOK * HD] = auxs * (float)NE;
}

// ---------------- launch ----------------
extern "C" void kernel_launch(void* const* d_in, const int* in_sizes, int n_in,
                              void* d_out, int out_size) {
    const float* x     = (const float*)d_in[0];
    const float* skin  = (const float*)d_in[1];
    const float* Wimg  = (const float*)d_in[2];
    const float* Wskin = (const float*)d_in[3];
    const float* W1    = (const float*)d_in[4];
    const float* b1    = (const float*)d_in[5];
    const float* W2    = (const float*)d_in[6];
    const float* b2    = (const float*)d_in[7];
    float* out = (float*)d_out;

    cudaFuncSetAttribute(k_gemm1, cudaFuncAttributeMaxDynamicSharedMemorySize, G1_SMEM);
    cudaFuncSetAttribute(k_gemm2, cudaFuncAttributeMaxDynamicSharedMemorySize, G2_SMEM);

    k_init<<<1, 256>>>();
    k_convert<<<2048, 256>>>(W1, W2);
    k_router<<<NTOK / RT, 256>>>(x, skin, Wimg, Wskin);
    k_gemm1<<<dim3(1, NTOK / 128, NE), 256, G1_SMEM>>>(b1);
    k_gemm2<<<dim3(HD / 128, NE, NSPLIT), 256, G2_SMEM>>>(b2);
    k_combine<<<NTOK, 256>>>(x, out);
    k_aux<<<1, 256>>>(out, out_size);
}